// round 16
// baseline (speedup 1.0000x reference)
#include <cuda_runtime.h>
#include <cstdint>

// ---------------- problem constants ----------------
#define BATCH 2
#define SEQ 2048
#define DMODEL 512
#define KDIM 256
#define VDIM 256
#define ODIM 512
#define NHEADS 8
#define HDIM 32
#define LOG2E 1.4426950408889634f
#define MTOT (BATCH * SEQ)          // 4096

// scratch
__device__ float g_q[MTOT * KDIM];
__device__ float g_k[MTOT * KDIM];
__device__ float g_vt[KDIM * MTOT];    // V projection, transposed: [n=256][m=4096]
__device__ float g_ctx[MTOT * VDIM];   // tf32-rounded context
__device__ float g_wqt[KDIM * DMODEL]; // Wq^T [256][512], tf32-rounded
__device__ float g_wkt[KDIM * DMODEL];
__device__ float g_wvt[VDIM * DMODEL];
__device__ float g_wot[ODIM * VDIM];   // Wo^T [512][256]

// ---------------- helpers ----------------
__device__ __forceinline__ uint32_t smem_u32(const void* p) {
    uint32_t a;
    asm("{ .reg .u64 t; cvta.to.shared.u64 t, %1; cvt.u32.u64 %0, t; }" : "=r"(a) : "l"(p));
    return a;
}
__device__ __forceinline__ float tf32r(float x) {
    float y; asm("cvt.rna.tf32.f32 %0, %1;" : "=f"(y) : "f"(x)); return y;
}
__device__ __forceinline__ float ex2f(float x) {
    float y; asm("ex2.approx.ftz.f32 %0, %1;" : "=f"(y) : "f"(x)); return y;
}
__device__ __forceinline__ void mma8(float* c, const uint32_t* a, uint32_t b0, uint32_t b1) {
    asm volatile(
        "mma.sync.aligned.m16n8k8.row.col.f32.tf32.tf32.f32 "
        "{%0,%1,%2,%3}, {%4,%5,%6,%7}, {%8,%9}, {%0,%1,%2,%3};"
        : "+f"(c[0]), "+f"(c[1]), "+f"(c[2]), "+f"(c[3])
        : "r"(a[0]), "r"(a[1]), "r"(a[2]), "r"(a[3]), "r"(b0), "r"(b1));
}
__device__ __forceinline__ void ldsm4(uint32_t* r, uint32_t a) {
    asm volatile("ldmatrix.sync.aligned.m8n8.x4.shared.b16 {%0,%1,%2,%3}, [%4];"
        : "=r"(r[0]), "=r"(r[1]), "=r"(r[2]), "=r"(r[3]) : "r"(a));
}
#define CP16(dst, src) \
    asm volatile("cp.async.ca.shared.global [%0], [%1], 16;" :: "r"(dst), "l"(src))
#define CPCOMMIT() asm volatile("cp.async.commit_group;" ::: "memory")
#define CPWAIT0()  asm volatile("cp.async.wait_group 0;" ::: "memory")
#define CPWAIT1()  asm volatile("cp.async.wait_group 1;" ::: "memory")
#define STS64(addr, v0, v1) \
    asm volatile("st.shared.v2.f32 [%0], {%1, %2};" :: "r"(addr), "f"(v0), "f"(v1))

#define SWZ(row, col) ((uint32_t)(col) ^ ((uint32_t)((row) & 7) << 4))

// ============================================================================
// Fused weight transpose + tf32 round for all four weights (one launch).
// ============================================================================
__global__ void wprep_all(const float* __restrict__ Wq, const float* __restrict__ Wk,
                          const float* __restrict__ Wv, const float* __restrict__ Wo)
{
    __shared__ float ts[32][33];
    const int z = blockIdx.z;
    const float* W; float* WT; int K, N;
    if (z == 0)      { W = Wq; WT = g_wqt; K = DMODEL; N = KDIM; }
    else if (z == 1) { W = Wk; WT = g_wkt; K = DMODEL; N = KDIM; }
    else if (z == 2) { W = Wv; WT = g_wvt; K = DMODEL; N = VDIM; }
    else             { W = Wo; WT = g_wot; K = VDIM;  N = ODIM; }

    const int n0 = blockIdx.x * 32, k0 = blockIdx.y * 32;
    if (n0 >= N || k0 >= K) return;
    const int tx = threadIdx.x, ty = threadIdx.y;   // 32 x 8
    #pragma unroll
    for (int i = 0; i < 4; i++)
        ts[ty + i * 8][tx] = W[(size_t)(k0 + ty + i * 8) * N + n0 + tx];
    __syncthreads();
    #pragma unroll
    for (int i = 0; i < 4; i++)
        WT[(size_t)(n0 + ty + i * 8) * K + k0 + tx] = tf32r(ts[tx][ty + i * 8]);
}

// ============================================================================
// GEMM core: 3-stage pipeline (R15, verified correct).
// ============================================================================
#define GEMM_SMEM 73728

template<bool PRE_A>
__device__ __forceinline__ void gemm_load(
    const float* __restrict__ A, const float* __restrict__ WT,
    int K, int m0, int n0, uint32_t sb, int kb, int stage, int tid)
{
    const uint32_t bd = sb + 49152 + stage * 8192;
    #pragma unroll
    for (int i = 0; i < 2; i++) {
        int idx = tid + i * 256;
        int n = idx >> 3, c = idx & 7;
        CP16(bd + n * 128 + SWZ(n, c * 16), WT + (size_t)(n0 + n) * K + kb * 32 + c * 4);
    }
    if (PRE_A) {
        const uint32_t ad = sb + stage * 16384;
        #pragma unroll
        for (int i = 0; i < 4; i++) {
            int idx = tid + i * 256;
            int r = idx >> 3, c = idx & 7;
            CP16(ad + r * 128 + SWZ(r, c * 16), A + (size_t)(m0 + r) * K + kb * 32 + c * 4);
        }
    }
    CPCOMMIT();
}

__device__ __forceinline__ void a_reg_load(
    const float* __restrict__ A, int K, int m0, int kb, int tid, float4* pa)
{
    #pragma unroll
    for (int i = 0; i < 4; i++) {
        int idx = tid + i * 256;
        int r = idx >> 3, c = idx & 7;
        pa[i] = *(const float4*)(A + (size_t)(m0 + r) * K + kb * 32 + c * 4);
    }
}
__device__ __forceinline__ void a_reg_store(
    char* smg, int stage, int tid, const float4* pa)
{
    char* ad = smg + stage * 16384;
    #pragma unroll
    for (int i = 0; i < 4; i++) {
        int idx = tid + i * 256;
        int r = idx >> 3, c = idx & 7;
        float4 v = pa[i];
        v.x = tf32r(v.x); v.y = tf32r(v.y); v.z = tf32r(v.z); v.w = tf32r(v.w);
        *(float4*)(ad + r * 128 + SWZ(r, c * 16)) = v;
    }
}

template<bool PRE_A>
__device__ __forceinline__ void gemm_body(
    const float* __restrict__ A, const float* __restrict__ WT,
    const float* __restrict__ bias, float* __restrict__ C,
    int M, int N, int K, float oscale, int mode,
    int m0, int n0, char* smg)
{
    const uint32_t sb = smem_u32(smg);
    const int tid = threadIdx.x;
    const int w = tid >> 5, lane = tid & 31;
    const int g = lane >> 2, t = lane & 3;
    const int wm = w >> 1, wn = w & 1;

    float acc[2][4][4];
    #pragma unroll
    for (int i = 0; i < 2; i++)
        #pragma unroll
        for (int j = 0; j < 4; j++)
            #pragma unroll
            for (int q = 0; q < 4; q++) acc[i][j][q] = 0.f;

    const int nkb = K >> 5;

    if (!PRE_A) {
        float4 pa[4];
        a_reg_load(A, K, m0, 0, tid, pa);
        a_reg_store(smg, 0, tid, pa);
        a_reg_load(A, K, m0, 1, tid, pa);
        a_reg_store(smg, 1, tid, pa);
    }
    gemm_load<PRE_A>(A, WT, K, m0, n0, sb, 0, 0, tid);
    gemm_load<PRE_A>(A, WT, K, m0, n0, sb, 1, 1, tid);

    for (int kb = 0; kb < nkb; kb++) {
        const int stage = kb % 3;
        if (kb == nkb - 1) CPWAIT0();   // last block: its group IS the newest
        else               CPWAIT1();
        __syncthreads();

        float4 pa[4];
        if (!PRE_A && kb + 2 < nkb)
            a_reg_load(A, K, m0, kb + 2, tid, pa);

        const uint32_t ab = sb + stage * 16384;
        const uint32_t bb = sb + 49152 + stage * 8192;
        #pragma unroll
        for (int kt = 0; kt < 4; kt++) {
            uint32_t af[2][4], bf[2][4];
            #pragma unroll
            for (int mt = 0; mt < 2; mt++) {
                int mr = wm * 32 + mt * 16 + (lane & 7) + ((lane >> 3) & 1) * 8;
                ldsm4(af[mt], ab + mr * 128 + SWZ(mr, kt * 32 + (lane >> 4) * 16));
            }
            #pragma unroll
            for (int p = 0; p < 2; p++) {
                int nr = wn * 32 + p * 16 + (lane & 7) + (lane >> 4) * 8;
                ldsm4(bf[p], bb + nr * 128 + SWZ(nr, kt * 32 + ((lane >> 3) & 1) * 16));
            }
            #pragma unroll
            for (int mt = 0; mt < 2; mt++)
                #pragma unroll
                for (int p = 0; p < 2; p++) {
                    mma8(acc[mt][2 * p],     af[mt], bf[p][0], bf[p][1]);
                    mma8(acc[mt][2 * p + 1], af[mt], bf[p][2], bf[p][3]);
                }
        }

        if (kb + 2 < nkb) {
            gemm_load<PRE_A>(A, WT, K, m0, n0, sb, kb + 2, (kb + 2) % 3, tid);
            if (!PRE_A)
                a_reg_store(smg, (kb + 2) % 3, tid, pa);
        }
    }

    #pragma unroll
    for (int nt = 0; nt < 4; nt++) {
        int col = n0 + wn * 32 + nt * 8 + 2 * t;
        float2 bv = *(const float2*)(bias + col);
        #pragma unroll
        for (int mt = 0; mt < 2; mt++) {
            int row = m0 + wm * 32 + mt * 16 + g;
            float o0 = acc[mt][nt][0] + bv.x, o1 = acc[mt][nt][1] + bv.y;
            float o2 = acc[mt][nt][2] + bv.x, o3 = acc[mt][nt][3] + bv.y;
            if (mode == 0) {
                *(float2*)(C + (size_t)row * N + col) =
                    make_float2(tf32r(o0 * oscale), tf32r(o1 * oscale));
                *(float2*)(C + (size_t)(row + 8) * N + col) =
                    make_float2(tf32r(o2 * oscale), tf32r(o3 * oscale));
            } else if (mode == 1) {
                C[(size_t)col * M + row]           = tf32r(o0);
                C[(size_t)(col + 1) * M + row]     = tf32r(o1);
                C[(size_t)col * M + row + 8]       = tf32r(o2);
                C[(size_t)(col + 1) * M + row + 8] = tf32r(o3);
            } else {
                *(float2*)(C + (size_t)row * N + col) = make_float2(o0, o1);
                *(float2*)(C + (size_t)(row + 8) * N + col) = make_float2(o2, o3);
            }
        }
    }
}

__global__ __launch_bounds__(256) void gemm_qkv(
    const float* __restrict__ Q, const float* __restrict__ K_,
    const float* __restrict__ V,
    const float* __restrict__ bq, const float* __restrict__ bk,
    const float* __restrict__ bv)
{
    extern __shared__ char smg[];
    const int z = blockIdx.z;
    const float* A; const float* WT; const float* bias; float* C;
    float oscale; int mode;
    if (z == 0)      { A = Q;  WT = g_wqt; bias = bq; C = g_q;  oscale = LOG2E / 16.0f; mode = 0; }
    else if (z == 1) { A = K_; WT = g_wkt; bias = bk; C = g_k;  oscale = 1.0f;          mode = 0; }
    else             { A = V;  WT = g_wvt; bias = bv; C = g_vt; oscale = 1.0f;          mode = 1; }
    gemm_body<false>(A, WT, bias, C, MTOT, KDIM, DMODEL, oscale, mode,
                     blockIdx.y * 128, blockIdx.x * 64, smg);
}

__global__ __launch_bounds__(256) void gemm_out(
    const float* __restrict__ bo, float* __restrict__ out)
{
    extern __shared__ char smg[];
    gemm_body<true>(g_ctx, g_wot, bo, out, MTOT, ODIM, VDIM, 1.0f, 2,
                    blockIdx.y * 128, blockIdx.x * 64, smg);
}

// ============================================================================
// Flash attention: R10 body, smem compacted to 64KB for 3 CTAs/SM.
// Layout: P 4x8KB @0 (overlays Q staging [0:16K), dead after qf extraction)
//         K 2x8KB @32768 | Vt 2x8KB @49152  => 64KB total.
// Extra __syncthreads after qf extraction closes Q-read vs P-write race.
// ============================================================================
#define ATTN_SMEM 65536

__global__ __launch_bounds__(128, 3) void attn_tc(
    const float* __restrict__ gq, const float* __restrict__ gk,
    const float* __restrict__ gvt, const float* __restrict__ mask,
    float* __restrict__ gctx)
{
    extern __shared__ char sma[];
    const uint32_t QB = smem_u32(sma);

    const int tid = threadIdx.x;
    const int w = tid >> 5, lane = tid & 31;
    const int g = lane >> 2, t = lane & 3;
    const int h = blockIdx.x, qt = blockIdx.y, b = blockIdx.z;

    const float* qsrc  = gq + ((size_t)(b * SEQ + qt * 128)) * KDIM + h * HDIM;
    const float* ksrc  = gk + ((size_t)(b * SEQ)) * KDIM + h * HDIM;
    const float* vtsrc = gvt + (size_t)(h * HDIM) * MTOT + b * SEQ;

    // prologue: Q (into [0:16K), later recycled as P), K0 @32768, V0 @49152
    #pragma unroll
    for (int i = 0; i < 8; i++) {
        int idx = tid + i * 128;
        int r = idx >> 3, c = idx & 7;
        CP16(QB + r * 128 + SWZ(r, c * 16), qsrc + (size_t)r * KDIM + c * 4);
    }
    #pragma unroll
    for (int i = 0; i < 4; i++) {
        int idx = tid + i * 128;
        int r = idx >> 3, c = idx & 7;
        CP16(QB + 32768 + r * 128 + SWZ(r, c * 16), ksrc + (size_t)r * KDIM + c * 4);
    }
    #pragma unroll
    for (int i = 0; i < 4; i++) {
        int idx = tid + i * 128;
        int r = idx >> 4, c = idx & 15;
        CP16(QB + 49152 + r * 256 + SWZ(r, c * 16), vtsrc + (size_t)r * MTOT + c * 4);
    }
    CPCOMMIT(); CPWAIT0();
    __syncthreads();

    // Q fragments (held in registers for whole kernel)
    uint32_t qf[2][4][4];
    #pragma unroll
    for (int mb = 0; mb < 2; mb++)
        #pragma unroll
        for (int kt = 0; kt < 4; kt++) {
            int mr = w * 32 + mb * 16 + (lane & 7) + ((lane >> 3) & 1) * 8;
            ldsm4(qf[mb][kt], QB + mr * 128 + SWZ(mr, kt * 32 + (lane >> 4) * 16));
        }
    __syncthreads();   // Q region now dead -> safe to reuse as P

    const float* mrow[2][2];
    #pragma unroll
    for (int mb = 0; mb < 2; mb++) {
        mrow[mb][0] = mask + (size_t)b * SEQ * SEQ
                    + (size_t)(qt * 128 + w * 32 + mb * 16 + g) * SEQ + 2 * t;
        mrow[mb][1] = mrow[mb][0] + (size_t)8 * SEQ;
    }

    float ctx[2][4][4];
    #pragma unroll
    for (int mb = 0; mb < 2; mb++)
        #pragma unroll
        for (int i = 0; i < 4; i++)
            #pragma unroll
            for (int j = 0; j < 4; j++) ctx[mb][i][j] = 0.f;
    float lsum[2][2] = {{0.f, 0.f}, {0.f, 0.f}};

    const uint32_t PB = QB + w * 8192;   // per-warp P: 32 rows x 256B, overlays Q
    const uint32_t pr = (lane & 7) + ((lane >> 3) & 1) * 8;
    const uint32_t pcol0 = (lane >> 4) * 16;
    const uint32_t pswz = (pr & 7) << 4;
    const uint32_t stswz = (uint32_t)(g & 7) << 4;

    for (int kt0 = 0; kt0 < 32; kt0++) {
        const int cur = kt0 & 1;

        if (kt0 < 31) {
            const uint32_t kd = QB + 32768 + (cur ^ 1) * 8192;
            const uint32_t vd = QB + 49152 + (cur ^ 1) * 8192;
            #pragma unroll
            for (int i = 0; i < 4; i++) {
                int idx = tid + i * 128;
                int r = idx >> 3, c = idx & 7;
                CP16(kd + r * 128 + SWZ(r, c * 16),
                     ksrc + (size_t)((kt0 + 1) * 64 + r) * KDIM + c * 4);
            }
            #pragma unroll
            for (int i = 0; i < 4; i++) {
                int idx = tid + i * 128;
                int r = idx >> 4, c = idx & 15;
                CP16(vd + r * 256 + SWZ(r, c * 16),
                     vtsrc + (size_t)r * MTOT + (kt0 + 1) * 64 + c * 4);
            }
            CPCOMMIT();
        }

        const uint32_t kbse = QB + 32768 + cur * 8192;

        #pragma unroll
        for (int nh = 0; nh < 2; nh++) {
            float2 mv[2][2][4];
            #pragma unroll
            for (int mb = 0; mb < 2; mb++)
                #pragma unroll
                for (int rh = 0; rh < 2; rh++)
                    #pragma unroll
                    for (int nb = 0; nb < 4; nb++)
                        mv[mb][rh][nb] = *(const float2*)(mrow[mb][rh] + kt0 * 64 + nh * 32 + nb * 8);

            float sc[2][4][4];
            #pragma unroll
            for (int mb = 0; mb < 2; mb++)
                #pragma unroll
                for (int i = 0; i < 4; i++)
                    #pragma unroll
                    for (int j = 0; j < 4; j++) sc[mb][i][j] = 0.f;

            #pragma unroll
            for (int kt = 0; kt < 4; kt++) {
                #pragma unroll
                for (int p = 0; p < 2; p++) {
                    int kr = nh * 32 + p * 16 + (lane & 7) + (lane >> 4) * 8;
                    uint32_t bf[4];
                    ldsm4(bf, kbse + kr * 128 + SWZ(kr, kt * 32 + ((lane >> 3) & 1) * 16));
                    #pragma unroll
                    for (int mb = 0; mb < 2; mb++) {
                        mma8(sc[mb][2 * p],     qf[mb][kt], bf[0], bf[1]);
                        mma8(sc[mb][2 * p + 1], qf[mb][kt], bf[2], bf[3]);
                    }
                }
            }

            #pragma unroll
            for (int mb = 0; mb < 2; mb++) {
                const uint32_t ps0 = PB + (uint32_t)(mb * 16 + g) * 256;
                const uint32_t ps1 = PB + (uint32_t)(mb * 16 + g + 8) * 256;
                #pragma unroll
                for (int nb = 0; nb < 4; nb++) {
                    float p0 = ex2f(__fmaf_rn(mv[mb][0][nb].x, LOG2E, sc[mb][nb][0]));
                    float p1 = ex2f(__fmaf_rn(mv[mb][0][nb].y, LOG2E, sc[mb][nb][1]));
                    float p2 = ex2f(__fmaf_rn(mv[mb][1][nb].x, LOG2E, sc[mb][nb][2]));
                    float p3 = ex2f(__fmaf_rn(mv[mb][1][nb].y, LOG2E, sc[mb][nb][3]));
                    lsum[mb][0] += p0 + p1;
                    lsum[mb][1] += p2 + p3;
                    uint32_t cb = (uint32_t)(nh * 128 + nb * 32 + t * 8);
                    STS64(ps0 + (cb ^ stswz), tf32r(p0), tf32r(p1));
                    STS64(ps1 + (cb ^ stswz), tf32r(p2), tf32r(p3));
                }
            }
        }
        __syncwarp();

        const uint32_t vbse = QB + 49152 + cur * 8192;
        #pragma unroll
        for (int kc = 0; kc < 8; kc++) {
            uint32_t a[2][4];
            #pragma unroll
            for (int mb = 0; mb < 2; mb++)
                ldsm4(a[mb], PB + (uint32_t)(mb * 16 + pr) * 256
                           + (((uint32_t)(kc * 32) + pcol0) ^ pswz));
            #pragma unroll
            for (int p = 0; p < 2; p++) {
                int dr = p * 16 + (lane & 7) + (lane >> 4) * 8;
                uint32_t bf[4];
                ldsm4(bf, vbse + dr * 256 + SWZ(dr, kc * 32 + ((lane >> 3) & 1) * 16));
                #pragma unroll
                for (int mb = 0; mb < 2; mb++) {
                    mma8(ctx[mb][2 * p],     a[mb], bf[0], bf[1]);
                    mma8(ctx[mb][2 * p + 1], a[mb], bf[2], bf[3]);
                }
            }
        }

        if (kt0 < 31) CPWAIT0();
        __syncthreads();
    }

    #pragma unroll
    for (int mb = 0; mb < 2; mb++)
        #pragma unroll
        for (int rh = 0; rh < 2; rh++) {
            float v = lsum[mb][rh];
            v += __shfl_xor_sync(0xFFFFFFFFu, v, 1);
            v += __shfl_xor_sync(0xFFFFFFFFu, v, 2);
            lsum[mb][rh] = 1.0f / v;
        }

    #pragma unroll
    for (int mb = 0; mb < 2; mb++) {
        size_t rbase = ((size_t)(b * SEQ + qt * 128 + w * 32 + mb * 16 + g)) * VDIM + h * HDIM;
        float ig = lsum[mb][0], ih = lsum[mb][1];
        #pragma unroll
        for (int nt = 0; nt < 4; nt++) {
            int col = nt * 8 + 2 * t;
            *(float2*)(gctx + rbase + col) =
                make_float2(tf32r(ctx[mb][nt][0] * ig), tf32r(ctx[mb][nt][1] * ig));
            *(float2*)(gctx + rbase + (size_t)8 * VDIM + col) =
                make_float2(tf32r(ctx[mb][nt][2] * ih), tf32r(ctx[mb][nt][3] * ih));
        }
    }
}

// ---------------- launch ----------------
extern "C" void kernel_launch(void* const* d_in, const int* in_sizes, int n_in,
                              void* d_out, int out_size)
{
    const float* V    = (const float*)d_in[0];
    const float* Q    = (const float*)d_in[1];
    const float* K    = (const float*)d_in[2];
    const float* mask = (const float*)d_in[3];
    const float* Wq   = (const float*)d_in[4];
    const float* bq   = (const float*)d_in[5];
    const float* Wk   = (const float*)d_in[6];
    const float* bk   = (const float*)d_in[7];
    const float* Wv   = (const float*)d_in[8];
    const float* bv   = (const float*)d_in[9];
    const float* Wo   = (const float*)d_in[10];
    const float* bo   = (const float*)d_in[11];
    float* out = (float*)d_out;

    float *dq, *dk, *dvt, *dctx;
    cudaGetSymbolAddress((void**)&dq,   g_q);
    cudaGetSymbolAddress((void**)&dk,   g_k);
    cudaGetSymbolAddress((void**)&dvt,  g_vt);
    cudaGetSymbolAddress((void**)&dctx, g_ctx);

    cudaFuncSetAttribute(gemm_qkv, cudaFuncAttributeMaxDynamicSharedMemorySize, GEMM_SMEM);
    cudaFuncSetAttribute(gemm_out, cudaFuncAttributeMaxDynamicSharedMemorySize, GEMM_SMEM);
    cudaFuncSetAttribute(attn_tc,  cudaFuncAttributeMaxDynamicSharedMemorySize, ATTN_SMEM);

    // 1) all weight transposes in one launch
    wprep_all<<<dim3(16, 16, 4), dim3(32, 8)>>>(Wq, Wk, Wv, Wo);

    // 2) fused QKV projections (3-stage pipelined GEMM, A RNA-rounded in regs)
    gemm_qkv<<<dim3(KDIM / 64, MTOT / 128, 3), 256, GEMM_SMEM>>>(Q, K, V, bq, bk, bv);

    // 3) attention (64KB smem -> 3 CTAs/SM, 12 warps/SM)
    attn_tc<<<dim3(NHEADS, SEQ / 128, BATCH), 128, ATTN_SMEM>>>(dq, dk, dvt, mask, dctx);

    // 4) output projection (all-cp.async 3-stage)
    gemm_out<<<dim3(ODIM / 64, MTOT / 128), 256, GEMM_SMEM>>>(bo, out);
}

// round 17
// speedup vs baseline: 1.6272x; 1.6272x over previous
#include <cuda_runtime.h>
#include <cstdint>

// ---------------- problem constants ----------------
#define BATCH 2
#define SEQ 2048
#define DMODEL 512
#define KDIM 256
#define VDIM 256
#define ODIM 512
#define NHEADS 8
#define HDIM 32
#define LOG2E 1.4426950408889634f
#define MTOT (BATCH * SEQ)          // 4096

// scratch
__device__ float g_q[MTOT * KDIM];
__device__ float g_k[MTOT * KDIM];
__device__ float g_vt[KDIM * MTOT];    // V projection, transposed: [n=256][m=4096]
__device__ float g_ctx[MTOT * VDIM];   // tf32-rounded context
__device__ float g_wqt[KDIM * DMODEL]; // Wq^T [256][512], tf32-rounded
__device__ float g_wkt[KDIM * DMODEL];
__device__ float g_wvt[VDIM * DMODEL];
__device__ float g_wot[ODIM * VDIM];   // Wo^T [512][256]

// ---------------- helpers ----------------
__device__ __forceinline__ uint32_t smem_u32(const void* p) {
    uint32_t a;
    asm("{ .reg .u64 t; cvta.to.shared.u64 t, %1; cvt.u32.u64 %0, t; }" : "=r"(a) : "l"(p));
    return a;
}
__device__ __forceinline__ float tf32r(float x) {
    float y; asm("cvt.rna.tf32.f32 %0, %1;" : "=f"(y) : "f"(x)); return y;
}
__device__ __forceinline__ float ex2f(float x) {
    float y; asm("ex2.approx.ftz.f32 %0, %1;" : "=f"(y) : "f"(x)); return y;
}
__device__ __forceinline__ void mma8(float* c, const uint32_t* a, uint32_t b0, uint32_t b1) {
    asm volatile(
        "mma.sync.aligned.m16n8k8.row.col.f32.tf32.tf32.f32 "
        "{%0,%1,%2,%3}, {%4,%5,%6,%7}, {%8,%9}, {%0,%1,%2,%3};"
        : "+f"(c[0]), "+f"(c[1]), "+f"(c[2]), "+f"(c[3])
        : "r"(a[0]), "r"(a[1]), "r"(a[2]), "r"(a[3]), "r"(b0), "r"(b1));
}
__device__ __forceinline__ void ldsm4(uint32_t* r, uint32_t a) {
    asm volatile("ldmatrix.sync.aligned.m8n8.x4.shared.b16 {%0,%1,%2,%3}, [%4];"
        : "=r"(r[0]), "=r"(r[1]), "=r"(r[2]), "=r"(r[3]) : "r"(a));
}
#define CP16(dst, src) \
    asm volatile("cp.async.ca.shared.global [%0], [%1], 16;" :: "r"(dst), "l"(src))
#define CPCOMMIT() asm volatile("cp.async.commit_group;" ::: "memory")
#define CPWAIT0()  asm volatile("cp.async.wait_group 0;" ::: "memory")
#define CPWAIT1()  asm volatile("cp.async.wait_group 1;" ::: "memory")
#define STS64(addr, v0, v1) \
    asm volatile("st.shared.v2.f32 [%0], {%1, %2};" :: "r"(addr), "f"(v0), "f"(v1))

#define SWZ(row, col) ((uint32_t)(col) ^ ((uint32_t)((row) & 7) << 4))

// ============================================================================
// Fused weight transpose + tf32 round for all four weights (one launch).
// ============================================================================
__global__ void wprep_all(const float* __restrict__ Wq, const float* __restrict__ Wk,
                          const float* __restrict__ Wv, const float* __restrict__ Wo)
{
    __shared__ float ts[32][33];
    const int z = blockIdx.z;
    const float* W; float* WT; int K, N;
    if (z == 0)      { W = Wq; WT = g_wqt; K = DMODEL; N = KDIM; }
    else if (z == 1) { W = Wk; WT = g_wkt; K = DMODEL; N = KDIM; }
    else if (z == 2) { W = Wv; WT = g_wvt; K = DMODEL; N = VDIM; }
    else             { W = Wo; WT = g_wot; K = VDIM;  N = ODIM; }

    const int n0 = blockIdx.x * 32, k0 = blockIdx.y * 32;
    if (n0 >= N || k0 >= K) return;
    const int tx = threadIdx.x, ty = threadIdx.y;   // 32 x 8
    #pragma unroll
    for (int i = 0; i < 4; i++)
        ts[ty + i * 8][tx] = W[(size_t)(k0 + ty + i * 8) * N + n0 + tx];
    __syncthreads();
    #pragma unroll
    for (int i = 0; i < 4; i++)
        WT[(size_t)(n0 + ty + i * 8) * K + k0 + tx] = tf32r(ts[tx][ty + i * 8]);
}

// ============================================================================
// GEMM core: 3-stage pipeline (R15, verified correct).
// ============================================================================
#define GEMM_SMEM 73728

template<bool PRE_A>
__device__ __forceinline__ void gemm_load(
    const float* __restrict__ A, const float* __restrict__ WT,
    int K, int m0, int n0, uint32_t sb, int kb, int stage, int tid)
{
    const uint32_t bd = sb + 49152 + stage * 8192;
    #pragma unroll
    for (int i = 0; i < 2; i++) {
        int idx = tid + i * 256;
        int n = idx >> 3, c = idx & 7;
        CP16(bd + n * 128 + SWZ(n, c * 16), WT + (size_t)(n0 + n) * K + kb * 32 + c * 4);
    }
    if (PRE_A) {
        const uint32_t ad = sb + stage * 16384;
        #pragma unroll
        for (int i = 0; i < 4; i++) {
            int idx = tid + i * 256;
            int r = idx >> 3, c = idx & 7;
            CP16(ad + r * 128 + SWZ(r, c * 16), A + (size_t)(m0 + r) * K + kb * 32 + c * 4);
        }
    }
    CPCOMMIT();
}

__device__ __forceinline__ void a_reg_load(
    const float* __restrict__ A, int K, int m0, int kb, int tid, float4* pa)
{
    #pragma unroll
    for (int i = 0; i < 4; i++) {
        int idx = tid + i * 256;
        int r = idx >> 3, c = idx & 7;
        pa[i] = *(const float4*)(A + (size_t)(m0 + r) * K + kb * 32 + c * 4);
    }
}
__device__ __forceinline__ void a_reg_store(
    char* smg, int stage, int tid, const float4* pa)
{
    char* ad = smg + stage * 16384;
    #pragma unroll
    for (int i = 0; i < 4; i++) {
        int idx = tid + i * 256;
        int r = idx >> 3, c = idx & 7;
        float4 v = pa[i];
        v.x = tf32r(v.x); v.y = tf32r(v.y); v.z = tf32r(v.z); v.w = tf32r(v.w);
        *(float4*)(ad + r * 128 + SWZ(r, c * 16)) = v;
    }
}

template<bool PRE_A>
__device__ __forceinline__ void gemm_body(
    const float* __restrict__ A, const float* __restrict__ WT,
    const float* __restrict__ bias, float* __restrict__ C,
    int M, int N, int K, float oscale, int mode,
    int m0, int n0, char* smg)
{
    const uint32_t sb = smem_u32(smg);
    const int tid = threadIdx.x;
    const int w = tid >> 5, lane = tid & 31;
    const int g = lane >> 2, t = lane & 3;
    const int wm = w >> 1, wn = w & 1;

    float acc[2][4][4];
    #pragma unroll
    for (int i = 0; i < 2; i++)
        #pragma unroll
        for (int j = 0; j < 4; j++)
            #pragma unroll
            for (int q = 0; q < 4; q++) acc[i][j][q] = 0.f;

    const int nkb = K >> 5;

    if (!PRE_A) {
        float4 pa[4];
        a_reg_load(A, K, m0, 0, tid, pa);
        a_reg_store(smg, 0, tid, pa);
        a_reg_load(A, K, m0, 1, tid, pa);
        a_reg_store(smg, 1, tid, pa);
    }
    gemm_load<PRE_A>(A, WT, K, m0, n0, sb, 0, 0, tid);
    gemm_load<PRE_A>(A, WT, K, m0, n0, sb, 1, 1, tid);

    for (int kb = 0; kb < nkb; kb++) {
        const int stage = kb % 3;
        if (kb == nkb - 1) CPWAIT0();   // last block: its group IS the newest
        else               CPWAIT1();
        __syncthreads();

        float4 pa[4];
        if (!PRE_A && kb + 2 < nkb)
            a_reg_load(A, K, m0, kb + 2, tid, pa);

        const uint32_t ab = sb + stage * 16384;
        const uint32_t bb = sb + 49152 + stage * 8192;
        #pragma unroll
        for (int kt = 0; kt < 4; kt++) {
            uint32_t af[2][4], bf[2][4];
            #pragma unroll
            for (int mt = 0; mt < 2; mt++) {
                int mr = wm * 32 + mt * 16 + (lane & 7) + ((lane >> 3) & 1) * 8;
                ldsm4(af[mt], ab + mr * 128 + SWZ(mr, kt * 32 + (lane >> 4) * 16));
            }
            #pragma unroll
            for (int p = 0; p < 2; p++) {
                int nr = wn * 32 + p * 16 + (lane & 7) + (lane >> 4) * 8;
                ldsm4(bf[p], bb + nr * 128 + SWZ(nr, kt * 32 + ((lane >> 3) & 1) * 16));
            }
            #pragma unroll
            for (int mt = 0; mt < 2; mt++)
                #pragma unroll
                for (int p = 0; p < 2; p++) {
                    mma8(acc[mt][2 * p],     af[mt], bf[p][0], bf[p][1]);
                    mma8(acc[mt][2 * p + 1], af[mt], bf[p][2], bf[p][3]);
                }
        }

        if (kb + 2 < nkb) {
            gemm_load<PRE_A>(A, WT, K, m0, n0, sb, kb + 2, (kb + 2) % 3, tid);
            if (!PRE_A)
                a_reg_store(smg, (kb + 2) % 3, tid, pa);
        }
    }

    #pragma unroll
    for (int nt = 0; nt < 4; nt++) {
        int col = n0 + wn * 32 + nt * 8 + 2 * t;
        float2 bv = *(const float2*)(bias + col);
        #pragma unroll
        for (int mt = 0; mt < 2; mt++) {
            int row = m0 + wm * 32 + mt * 16 + g;
            float o0 = acc[mt][nt][0] + bv.x, o1 = acc[mt][nt][1] + bv.y;
            float o2 = acc[mt][nt][2] + bv.x, o3 = acc[mt][nt][3] + bv.y;
            if (mode == 0) {
                *(float2*)(C + (size_t)row * N + col) =
                    make_float2(tf32r(o0 * oscale), tf32r(o1 * oscale));
                *(float2*)(C + (size_t)(row + 8) * N + col) =
                    make_float2(tf32r(o2 * oscale), tf32r(o3 * oscale));
            } else if (mode == 1) {
                C[(size_t)col * M + row]           = tf32r(o0);
                C[(size_t)(col + 1) * M + row]     = tf32r(o1);
                C[(size_t)col * M + row + 8]       = tf32r(o2);
                C[(size_t)(col + 1) * M + row + 8] = tf32r(o3);
            } else {
                *(float2*)(C + (size_t)row * N + col) = make_float2(o0, o1);
                *(float2*)(C + (size_t)(row + 8) * N + col) = make_float2(o2, o3);
            }
        }
    }
}

__global__ __launch_bounds__(256) void gemm_qkv(
    const float* __restrict__ Q, const float* __restrict__ K_,
    const float* __restrict__ V,
    const float* __restrict__ bq, const float* __restrict__ bk,
    const float* __restrict__ bv)
{
    extern __shared__ char smg[];
    const int z = blockIdx.z;
    const float* A; const float* WT; const float* bias; float* C;
    float oscale; int mode;
    if (z == 0)      { A = Q;  WT = g_wqt; bias = bq; C = g_q;  oscale = LOG2E / 16.0f; mode = 0; }
    else if (z == 1) { A = K_; WT = g_wkt; bias = bk; C = g_k;  oscale = 1.0f;          mode = 0; }
    else             { A = V;  WT = g_wvt; bias = bv; C = g_vt; oscale = 1.0f;          mode = 1; }
    gemm_body<false>(A, WT, bias, C, MTOT, KDIM, DMODEL, oscale, mode,
                     blockIdx.y * 128, blockIdx.x * 64, smg);
}

__global__ __launch_bounds__(256) void gemm_out(
    const float* __restrict__ bo, float* __restrict__ out)
{
    extern __shared__ char smg[];
    gemm_body<true>(g_ctx, g_wot, bo, out, MTOT, ODIM, VDIM, 1.0f, 2,
                    blockIdx.y * 128, blockIdx.x * 64, smg);
}

// ============================================================================
// Flash attention: compact 64KB smem (P overlays dead Q staging) so a third
// CTA/SM is POSSIBLE, but launch_bounds(128,2) so ptxas never spills to force
// it (R16 lesson: forced occupancy = spills). Per-mb mask loads lower natural
// register pressure toward the 3-CTA threshold (~168 regs).
// Layout: P 4x8KB @0 | K 2x8KB @32768 | Vt 2x8KB @49152 = 64KB.
// ============================================================================
#define ATTN_SMEM 65536

__global__ __launch_bounds__(128, 2) void attn_tc(
    const float* __restrict__ gq, const float* __restrict__ gk,
    const float* __restrict__ gvt, const float* __restrict__ mask,
    float* __restrict__ gctx)
{
    extern __shared__ char sma[];
    const uint32_t QB = smem_u32(sma);

    const int tid = threadIdx.x;
    const int w = tid >> 5, lane = tid & 31;
    const int g = lane >> 2, t = lane & 3;
    const int h = blockIdx.x, qt = blockIdx.y, b = blockIdx.z;

    const float* qsrc  = gq + ((size_t)(b * SEQ + qt * 128)) * KDIM + h * HDIM;
    const float* ksrc  = gk + ((size_t)(b * SEQ)) * KDIM + h * HDIM;
    const float* vtsrc = gvt + (size_t)(h * HDIM) * MTOT + b * SEQ;

    // prologue: Q (into [0:16K), later recycled as P), K0 @32768, V0 @49152
    #pragma unroll
    for (int i = 0; i < 8; i++) {
        int idx = tid + i * 128;
        int r = idx >> 3, c = idx & 7;
        CP16(QB + r * 128 + SWZ(r, c * 16), qsrc + (size_t)r * KDIM + c * 4);
    }
    #pragma unroll
    for (int i = 0; i < 4; i++) {
        int idx = tid + i * 128;
        int r = idx >> 3, c = idx & 7;
        CP16(QB + 32768 + r * 128 + SWZ(r, c * 16), ksrc + (size_t)r * KDIM + c * 4);
    }
    #pragma unroll
    for (int i = 0; i < 4; i++) {
        int idx = tid + i * 128;
        int r = idx >> 4, c = idx & 15;
        CP16(QB + 49152 + r * 256 + SWZ(r, c * 16), vtsrc + (size_t)r * MTOT + c * 4);
    }
    CPCOMMIT(); CPWAIT0();
    __syncthreads();

    // Q fragments (held in registers for whole kernel)
    uint32_t qf[2][4][4];
    #pragma unroll
    for (int mb = 0; mb < 2; mb++)
        #pragma unroll
        for (int kt = 0; kt < 4; kt++) {
            int mr = w * 32 + mb * 16 + (lane & 7) + ((lane >> 3) & 1) * 8;
            ldsm4(qf[mb][kt], QB + mr * 128 + SWZ(mr, kt * 32 + (lane >> 4) * 16));
        }
    __syncthreads();   // Q region now dead -> safe to reuse as P

    const float* mbase = mask + (size_t)b * SEQ * SEQ
                       + (size_t)(qt * 128 + w * 32 + g) * SEQ + 2 * t;

    float ctx[2][4][4];
    #pragma unroll
    for (int mb = 0; mb < 2; mb++)
        #pragma unroll
        for (int i = 0; i < 4; i++)
            #pragma unroll
            for (int j = 0; j < 4; j++) ctx[mb][i][j] = 0.f;
    float lsum[2][2] = {{0.f, 0.f}, {0.f, 0.f}};

    const uint32_t PB = QB + w * 8192;   // per-warp P: 32 rows x 256B, overlays Q
    const uint32_t pr = (lane & 7) + ((lane >> 3) & 1) * 8;
    const uint32_t pcol0 = (lane >> 4) * 16;
    const uint32_t pswz = (pr & 7) << 4;
    const uint32_t stswz = (uint32_t)(g & 7) << 4;

    for (int kt0 = 0; kt0 < 32; kt0++) {
        const int cur = kt0 & 1;

        if (kt0 < 31) {
            const uint32_t kd = QB + 32768 + (cur ^ 1) * 8192;
            const uint32_t vd = QB + 49152 + (cur ^ 1) * 8192;
            #pragma unroll
            for (int i = 0; i < 4; i++) {
                int idx = tid + i * 128;
                int r = idx >> 3, c = idx & 7;
                CP16(kd + r * 128 + SWZ(r, c * 16),
                     ksrc + (size_t)((kt0 + 1) * 64 + r) * KDIM + c * 4);
            }
            #pragma unroll
            for (int i = 0; i < 4; i++) {
                int idx = tid + i * 128;
                int r = idx >> 4, c = idx & 15;
                CP16(vd + r * 256 + SWZ(r, c * 16),
                     vtsrc + (size_t)r * MTOT + (kt0 + 1) * 64 + c * 4);
            }
            CPCOMMIT();
        }

        const uint32_t kbse = QB + 32768 + cur * 8192;

        #pragma unroll
        for (int nh = 0; nh < 2; nh++) {
            float sc[2][4][4];
            #pragma unroll
            for (int mb = 0; mb < 2; mb++)
                #pragma unroll
                for (int i = 0; i < 4; i++)
                    #pragma unroll
                    for (int j = 0; j < 4; j++) sc[mb][i][j] = 0.f;

            #pragma unroll
            for (int kt = 0; kt < 4; kt++) {
                #pragma unroll
                for (int p = 0; p < 2; p++) {
                    int kr = nh * 32 + p * 16 + (lane & 7) + (lane >> 4) * 8;
                    uint32_t bf[4];
                    ldsm4(bf, kbse + kr * 128 + SWZ(kr, kt * 32 + ((lane >> 3) & 1) * 16));
                    #pragma unroll
                    for (int mb = 0; mb < 2; mb++) {
                        mma8(sc[mb][2 * p],     qf[mb][kt], bf[0], bf[1]);
                        mma8(sc[mb][2 * p + 1], qf[mb][kt], bf[2], bf[3]);
                    }
                }
            }

            // exp + P store; mask loaded per-mb to cap live registers
            #pragma unroll
            for (int mb = 0; mb < 2; mb++) {
                float2 mv[2][4];
                #pragma unroll
                for (int rh = 0; rh < 2; rh++)
                    #pragma unroll
                    for (int nb = 0; nb < 4; nb++)
                        mv[rh][nb] = *(const float2*)(mbase
                            + (size_t)(mb * 16 + rh * 8) * SEQ + kt0 * 64 + nh * 32 + nb * 8);

                const uint32_t ps0 = PB + (uint32_t)(mb * 16 + g) * 256;
                #pragma unroll
                for (int nb = 0; nb < 4; nb++) {
                    float p0 = ex2f(__fmaf_rn(mv[0][nb].x, LOG2E, sc[mb][nb][0]));
                    float p1 = ex2f(__fmaf_rn(mv[0][nb].y, LOG2E, sc[mb][nb][1]));
                    float p2 = ex2f(__fmaf_rn(mv[1][nb].x, LOG2E, sc[mb][nb][2]));
                    float p3 = ex2f(__fmaf_rn(mv[1][nb].y, LOG2E, sc[mb][nb][3]));
                    lsum[mb][0] += p0 + p1;
                    lsum[mb][1] += p2 + p3;
                    uint32_t cb = (uint32_t)(nh * 128 + nb * 32 + t * 8) ^ stswz;
                    STS64(ps0 + cb,            tf32r(p0), tf32r(p1));
                    STS64(ps0 + 2048 + cb,     tf32r(p2), tf32r(p3));   // row g+8
                }
            }
        }
        __syncwarp();

        const uint32_t vbse = QB + 49152 + cur * 8192;
        #pragma unroll
        for (int kc = 0; kc < 8; kc++) {
            uint32_t a[2][4];
            #pragma unroll
            for (int mb = 0; mb < 2; mb++)
                ldsm4(a[mb], PB + (uint32_t)(mb * 16 + pr) * 256
                           + (((uint32_t)(kc * 32) + pcol0) ^ pswz));
            #pragma unroll
            for (int p = 0; p < 2; p++) {
                int dr = p * 16 + (lane & 7) + (lane >> 4) * 8;
                uint32_t bf[4];
                ldsm4(bf, vbse + dr * 256 + SWZ(dr, kc * 32 + ((lane >> 3) & 1) * 16));
                #pragma unroll
                for (int mb = 0; mb < 2; mb++) {
                    mma8(ctx[mb][2 * p],     a[mb], bf[0], bf[1]);
                    mma8(ctx[mb][2 * p + 1], a[mb], bf[2], bf[3]);
                }
            }
        }

        if (kt0 < 31) CPWAIT0();
        __syncthreads();
    }

    #pragma unroll
    for (int mb = 0; mb < 2; mb++)
        #pragma unroll
        for (int rh = 0; rh < 2; rh++) {
            float v = lsum[mb][rh];
            v += __shfl_xor_sync(0xFFFFFFFFu, v, 1);
            v += __shfl_xor_sync(0xFFFFFFFFu, v, 2);
            lsum[mb][rh] = 1.0f / v;
        }

    #pragma unroll
    for (int mb = 0; mb < 2; mb++) {
        size_t rbase = ((size_t)(b * SEQ + qt * 128 + w * 32 + mb * 16 + g)) * VDIM + h * HDIM;
        float ig = lsum[mb][0], ih = lsum[mb][1];
        #pragma unroll
        for (int nt = 0; nt < 4; nt++) {
            int col = nt * 8 + 2 * t;
            *(float2*)(gctx + rbase + col) =
                make_float2(tf32r(ctx[mb][nt][0] * ig), tf32r(ctx[mb][nt][1] * ig));
            *(float2*)(gctx + rbase + (size_t)8 * VDIM + col) =
                make_float2(tf32r(ctx[mb][nt][2] * ih), tf32r(ctx[mb][nt][3] * ih));
        }
    }
}

// ---------------- launch ----------------
extern "C" void kernel_launch(void* const* d_in, const int* in_sizes, int n_in,
                              void* d_out, int out_size)
{
    const float* V    = (const float*)d_in[0];
    const float* Q    = (const float*)d_in[1];
    const float* K    = (const float*)d_in[2];
    const float* mask = (const float*)d_in[3];
    const float* Wq   = (const float*)d_in[4];
    const float* bq   = (const float*)d_in[5];
    const float* Wk   = (const float*)d_in[6];
    const float* bk   = (const float*)d_in[7];
    const float* Wv   = (const float*)d_in[8];
    const float* bv   = (const float*)d_in[9];
    const float* Wo   = (const float*)d_in[10];
    const float* bo   = (const float*)d_in[11];
    float* out = (float*)d_out;

    float *dq, *dk, *dvt, *dctx;
    cudaGetSymbolAddress((void**)&dq,   g_q);
    cudaGetSymbolAddress((void**)&dk,   g_k);
    cudaGetSymbolAddress((void**)&dvt,  g_vt);
    cudaGetSymbolAddress((void**)&dctx, g_ctx);

    cudaFuncSetAttribute(gemm_qkv, cudaFuncAttributeMaxDynamicSharedMemorySize, GEMM_SMEM);
    cudaFuncSetAttribute(gemm_out, cudaFuncAttributeMaxDynamicSharedMemorySize, GEMM_SMEM);
    cudaFuncSetAttribute(attn_tc,  cudaFuncAttributeMaxDynamicSharedMemorySize, ATTN_SMEM);

    // 1) all weight transposes in one launch
    wprep_all<<<dim3(16, 16, 4), dim3(32, 8)>>>(Wq, Wk, Wv, Wo);

    // 2) fused QKV projections (3-stage pipelined GEMM, A RNA-rounded in regs)
    gemm_qkv<<<dim3(KDIM / 64, MTOT / 128, 3), 256, GEMM_SMEM>>>(Q, K, V, bq, bk, bv);

    // 3) attention (64KB smem; 3 CTAs/SM if regs allow, else 2 — never spills)
    attn_tc<<<dim3(NHEADS, SEQ / 128, BATCH), 128, ATTN_SMEM>>>(dq, dk, dvt, mask, dctx);

    // 4) output projection (all-cp.async 3-stage)
    gemm_out<<<dim3(ODIM / 64, MTOT / 128), 256, GEMM_SMEM>>>(bo, out);
}